// round 1
// baseline (speedup 1.0000x reference)
#include <cuda_runtime.h>
#include <cstdint>
#include <cstdio>

// ---------------------------------------------------------------------------
// Problem constants
// ---------------------------------------------------------------------------
#define NMAX 200192        // >= N (=200000) and >= M
#define NBLK_STATS 240
#define BN_EPS 1e-4

// ---------------------------------------------------------------------------
// Static device scratch (allocation-free rule: __device__ globals)
// ---------------------------------------------------------------------------
__device__ float  g_t0[(NMAX + 1) * 32];   // bn1(feat), padded
__device__ float  g_x1[NMAX * 32];         // sub1 out (skip)
__device__ float  g_t1[(NMAX + 1) * 32];   // bn2(x1), padded
__device__ float  g_xc0[NMAX * 64];        // down out
__device__ float  g_t2[(NMAX + 1) * 64];   // bn3(xc0), padded
__device__ float  g_xc1[NMAX * 64];        // sub2 out
__device__ float  g_t3[(NMAX + 1) * 64];   // bn4(xc1), padded
__device__ float  g_xf[NMAX * 32];         // deconv out
__device__ float  g_t4[(NMAX + 1) * 64];   // bn5(concat), padded
__device__ double g_part[NBLK_STATS * 128];
__device__ float  g_scale[5 * 64];
__device__ float  g_shift[5 * 64];

// ---------------------------------------------------------------------------
// Packed fp32x2 FMA (sm_103a; only reachable via PTX)
// ---------------------------------------------------------------------------
__device__ __forceinline__ unsigned long long fma2(unsigned long long a,
                                                   unsigned long long b,
                                                   unsigned long long c) {
    unsigned long long d;
    asm("fma.rn.f32x2 %0, %1, %2, %3;" : "=l"(d) : "l"(a), "l"(b), "l"(c));
    return d;
}
__device__ __forceinline__ unsigned long long pack2(float x) {
    unsigned long long r;
    asm("mov.b64 %0, {%1, %1};" : "=l"(r) : "f"(x));
    return r;
}

// ---------------------------------------------------------------------------
// BN stats pass 1: deterministic per-block partial sums (double)
// partial layout: [blk][0:64]=sum, [blk][64:128]=sumsq  (channel-major)
// ---------------------------------------------------------------------------
template <int C>
__global__ __launch_bounds__(256) void bn_stats1(const float* __restrict__ x,
                                                 int rows,
                                                 double* __restrict__ partial) {
    __shared__ double ss[256], sq[256];
    int tid = threadIdx.x;
    long long total = (long long)rows * C;
    double s = 0.0, q = 0.0;
    for (long long i = (long long)blockIdx.x * 256 + tid; i < total;
         i += (long long)gridDim.x * 256) {
        double v = (double)x[i];
        s += v;
        q += v * v;
    }
    ss[tid] = s;
    sq[tid] = q;
    for (int st = 128; st >= C; st >>= 1) {
        __syncthreads();
        if (tid < st) { ss[tid] += ss[tid + st]; sq[tid] += sq[tid + st]; }
    }
    if (tid < C) {
        partial[blockIdx.x * 128 + tid]      = ss[tid];
        partial[blockIdx.x * 128 + 64 + tid] = sq[tid];
    }
}

// BN stats pass 2: reduce partials, emit scale/shift
__global__ void bn_stats2(const double* __restrict__ partial, int nblk, int rows,
                          const float* __restrict__ g, const float* __restrict__ b,
                          float* __restrict__ sc, float* __restrict__ sh, int C) {
    int c = threadIdx.x;
    if (c >= C) return;
    double s = 0.0, q = 0.0;
    for (int i = 0; i < nblk; i++) {
        s += partial[i * 128 + c];
        q += partial[i * 128 + 64 + c];
    }
    double mean = s / rows;
    double var  = q / rows - mean * mean;
    double inv  = 1.0 / sqrt(var + BN_EPS);
    double scale = (double)g[c] * inv;
    sc[c] = (float)scale;
    sh[c] = (float)((double)b[c] - mean * scale);
}

// ---------------------------------------------------------------------------
// BN apply + ReLU, writes padded buffer (pad row zeroed)
// ---------------------------------------------------------------------------
template <int C>
__global__ __launch_bounds__(256) void bn_apply(const float* __restrict__ x,
                                                float* __restrict__ y,
                                                const float* __restrict__ sc,
                                                const float* __restrict__ sh,
                                                int rows) {
    int i = blockIdx.x * blockDim.x + threadIdx.x;
    if (i < C / 4) {
        *reinterpret_cast<float4*>(&y[(size_t)rows * C + 4 * i]) =
            make_float4(0.f, 0.f, 0.f, 0.f);
    }
    int n4 = rows * C / 4;
    if (i < n4) {
        float4 d = reinterpret_cast<const float4*>(x)[i];
        int c0 = (i * 4) % C;
        d.x = fmaxf(fmaf(d.x, __ldg(&sc[c0 + 0]), __ldg(&sh[c0 + 0])), 0.f);
        d.y = fmaxf(fmaf(d.y, __ldg(&sc[c0 + 1]), __ldg(&sh[c0 + 1])), 0.f);
        d.z = fmaxf(fmaf(d.z, __ldg(&sc[c0 + 2]), __ldg(&sh[c0 + 2])), 0.f);
        d.w = fmaxf(fmaf(d.w, __ldg(&sc[c0 + 3]), __ldg(&sh[c0 + 3])), 0.f);
        reinterpret_cast<float4*>(y)[i] = d;
    }
}

// BN apply for concat(skip=x1[:,:32], xf[:,:32]) -> y [rows+1][64]
__global__ __launch_bounds__(256) void bn_apply_cat(const float* __restrict__ x1,
                                                    const float* __restrict__ xf,
                                                    float* __restrict__ y,
                                                    const float* __restrict__ sc,
                                                    const float* __restrict__ sh,
                                                    int rows) {
    int i = blockIdx.x * blockDim.x + threadIdx.x;
    if (i < 16) {
        *reinterpret_cast<float4*>(&y[(size_t)rows * 64 + 4 * i]) =
            make_float4(0.f, 0.f, 0.f, 0.f);
    }
    int n4 = rows * 16;  // float4 groups
    if (i < n4) {
        int row = i / 16, q = i % 16;
        float4 d = (q < 8) ? reinterpret_cast<const float4*>(x1)[row * 8 + q]
                           : reinterpret_cast<const float4*>(xf)[row * 8 + (q - 8)];
        int c0 = q * 4;
        d.x = fmaxf(fmaf(d.x, __ldg(&sc[c0 + 0]), __ldg(&sh[c0 + 0])), 0.f);
        d.y = fmaxf(fmaf(d.y, __ldg(&sc[c0 + 1]), __ldg(&sh[c0 + 1])), 0.f);
        d.z = fmaxf(fmaf(d.z, __ldg(&sc[c0 + 2]), __ldg(&sh[c0 + 2])), 0.f);
        d.w = fmaxf(fmaf(d.w, __ldg(&sc[c0 + 3]), __ldg(&sh[c0 + 3])), 0.f);
        reinterpret_cast<float4*>(y)[i] = d;
    }
}

// ---------------------------------------------------------------------------
// Gather-GEMM sparse conv:
//   out[m, co] = sum_k sum_ci fpad[nbr[k*rows+m], ci] * W[k, ci, co]
// fpad has P+1 rows, row P = zeros (sentinel). 64-row tile/block, 256 thr.
// Thread (tid): row r = tid>>2; couts { (tid&3)*4 + j*16 + [0..3] }.
// ---------------------------------------------------------------------------
template <int CIN, int COUT, int K>
__global__ __launch_bounds__(256) void conv_kernel(const float* __restrict__ fpad,
                                                   const int* __restrict__ nbr,
                                                   const float* __restrict__ W,
                                                   float* __restrict__ out,
                                                   int rows, int P) {
    __shared__ __align__(16) float Xs[64][CIN + 4];
    __shared__ __align__(16) float Ws[CIN][COUT];
    __shared__ int idx_s[64];

    constexpr int NJ = COUT / 16;  // cout groups of 16 per thread-quad
    int tid  = threadIdx.x;
    int row0 = blockIdx.x * 64;
    int r    = tid >> 2;
    int csub = (tid & 3) * 4;

    unsigned long long acc[NJ * 2];
#pragma unroll
    for (int i = 0; i < NJ * 2; i++) acc[i] = 0ull;

    for (int k = 0; k < K; k++) {
        if (tid < 64) {
            int gr = row0 + tid;
            idx_s[tid] = (gr < rows) ? nbr[(size_t)k * rows + gr] : P;
        }
        __syncthreads();
        // gather A tile
        constexpr int SEG = CIN / 4;
        for (int v = tid; v < 64 * SEG; v += 256) {
            int rr = v / SEG, s = v % SEG;
            float4 val = reinterpret_cast<const float4*>(
                fpad + (size_t)idx_s[rr] * CIN)[s];
            *reinterpret_cast<float4*>(&Xs[rr][s * 4]) = val;
        }
        // stage tap weights (flat: pitch == COUT)
        const float4* Wk = reinterpret_cast<const float4*>(W + (size_t)k * CIN * COUT);
        for (int v = tid; v < CIN * COUT / 4; v += 256) {
            reinterpret_cast<float4*>(&Ws[0][0])[v] = Wk[v];
        }
        __syncthreads();

#pragma unroll
        for (int c4 = 0; c4 < CIN / 4; c4++) {
            float4 xv = *reinterpret_cast<const float4*>(&Xs[r][c4 * 4]);
#pragma unroll
            for (int ci = 0; ci < 4; ci++) {
                float xs = (ci == 0) ? xv.x : (ci == 1) ? xv.y : (ci == 2) ? xv.z : xv.w;
                unsigned long long xx = pack2(xs);
#pragma unroll
                for (int j = 0; j < NJ; j++) {
                    ulonglong2 w = *reinterpret_cast<const ulonglong2*>(
                        &Ws[c4 * 4 + ci][csub + j * 16]);
                    acc[2 * j + 0] = fma2(xx, w.x, acc[2 * j + 0]);
                    acc[2 * j + 1] = fma2(xx, w.y, acc[2 * j + 1]);
                }
            }
        }
        __syncthreads();
    }

    int orow = row0 + r;
    if (orow < rows) {
#pragma unroll
        for (int j = 0; j < NJ; j++) {
            float2 a = *reinterpret_cast<float2*>(&acc[2 * j + 0]);
            float2 b = *reinterpret_cast<float2*>(&acc[2 * j + 1]);
            *reinterpret_cast<float4*>(&out[(size_t)orow * COUT + csub + j * 16]) =
                make_float4(a.x, a.y, b.x, b.y);
        }
    }
}

// ---------------------------------------------------------------------------
// Stride-2 transpose conv (deconv): out[n] = g[up_cidx[n]] @ W[up_k[n]]
// Two predicated passes over k (4 taps of W fit 32KB smem each).
// ---------------------------------------------------------------------------
__global__ __launch_bounds__(256) void deconv_kernel(const float* __restrict__ g,
                                                     const int* __restrict__ up_cidx,
                                                     const int* __restrict__ up_k,
                                                     const float* __restrict__ Wup,
                                                     float* __restrict__ out,
                                                     int nrows, int kbase) {
    __shared__ float Ws[4][64][32];  // 32 KB
    int tid = threadIdx.x;
    const float4* src = reinterpret_cast<const float4*>(Wup + (size_t)kbase * 64 * 32);
    for (int v = tid; v < 4 * 64 * 32 / 4; v += 256)
        reinterpret_cast<float4*>(&Ws[0][0][0])[v] = src[v];
    __syncthreads();

    int warp = tid >> 5, lane = tid & 31;
    int base = blockIdx.x * 64 + warp * 8;
#pragma unroll
    for (int i = 0; i < 8; i++) {
        int row = base + i;
        if (row >= nrows) break;
        int k = up_k[row] - kbase;
        if ((unsigned)k < 4u) {
            int cid = up_cidx[row];
            const float* grow = g + (size_t)cid * 64;
            float xa = grow[lane], xb = grow[lane + 32];
            float acc = 0.f;
#pragma unroll
            for (int cin = 0; cin < 64; cin++) {
                float xv = __shfl_sync(0xFFFFFFFFu, (cin < 32) ? xa : xb, cin & 31);
                acc = fmaf(xv, Ws[k][cin][lane], acc);
            }
            out[(size_t)row * 32 + lane] = acc;
        }
    }
}

// ---------------------------------------------------------------------------
// Host launcher
// ---------------------------------------------------------------------------
static void* sym_addr(const void* s) {
    void* p = nullptr;
    cudaGetSymbolAddress(&p, s);
    return p;
}

extern "C" void kernel_launch(void* const* d_in, const int* in_sizes, int n_in,
                              void* d_out, int out_size) {
    const float* feat    = (const float*)d_in[0];
    const float* w_sub1  = (const float*)d_in[1];
    const float* w_down  = (const float*)d_in[2];
    const float* w_sub2  = (const float*)d_in[3];
    const float* w_up    = (const float*)d_in[4];
    const float* w_sub3  = (const float*)d_in[5];
    const float* g1 = (const float*)d_in[6];  const float* b1 = (const float*)d_in[7];
    const float* g2 = (const float*)d_in[8];  const float* b2 = (const float*)d_in[9];
    const float* g3 = (const float*)d_in[10]; const float* b3 = (const float*)d_in[11];
    const float* g4 = (const float*)d_in[12]; const float* b4 = (const float*)d_in[13];
    const float* g5 = (const float*)d_in[14]; const float* b5 = (const float*)d_in[15];
    const int* nbr_fine   = (const int*)d_in[16];
    const int* nbr_coarse = (const int*)d_in[17];
    const int* down_idx   = (const int*)d_in[18];
    const int* up_cidx    = (const int*)d_in[19];
    const int* up_k       = (const int*)d_in[20];

    int N = in_sizes[0] / 32;
    int M = in_sizes[18] / 8;

    float*  t0   = (float*)sym_addr(g_t0);
    float*  x1   = (float*)sym_addr(g_x1);
    float*  t1   = (float*)sym_addr(g_t1);
    float*  xc0  = (float*)sym_addr(g_xc0);
    float*  t2   = (float*)sym_addr(g_t2);
    float*  xc1  = (float*)sym_addr(g_xc1);
    float*  t3   = (float*)sym_addr(g_t3);
    float*  xf   = (float*)sym_addr(g_xf);
    float*  t4   = (float*)sym_addr(g_t4);
    double* part = (double*)sym_addr(g_part);
    float*  sc   = (float*)sym_addr(g_scale);
    float*  sh   = (float*)sym_addr(g_shift);
    float*  outp = (float*)d_out;

    auto cdiv = [](int a, int b) { return (a + b - 1) / b; };

    // stage 1: BN1(feat) -> t0 ; sub1 -> x1
    bn_stats1<32><<<NBLK_STATS, 256>>>(feat, N, part);
    bn_stats2<<<1, 64>>>(part, NBLK_STATS, N, g1, b1, sc + 0 * 64, sh + 0 * 64, 32);
    bn_apply<32><<<cdiv(N * 32 / 4, 256), 256>>>(feat, t0, sc + 0 * 64, sh + 0 * 64, N);
    conv_kernel<32, 32, 27><<<cdiv(N, 64), 256>>>(t0, nbr_fine, w_sub1, x1, N, N);

    // stage 2: BN2(x1) -> t1 ; down -> xc0
    bn_stats1<32><<<NBLK_STATS, 256>>>(x1, N, part);
    bn_stats2<<<1, 64>>>(part, NBLK_STATS, N, g2, b2, sc + 1 * 64, sh + 1 * 64, 32);
    bn_apply<32><<<cdiv(N * 32 / 4, 256), 256>>>(x1, t1, sc + 1 * 64, sh + 1 * 64, N);
    conv_kernel<32, 64, 8><<<cdiv(M, 64), 256>>>(t1, down_idx, w_down, xc0, M, N);

    // stage 3: BN3(xc0) -> t2 ; sub2 -> xc1
    bn_stats1<64><<<NBLK_STATS, 256>>>(xc0, M, part);
    bn_stats2<<<1, 64>>>(part, NBLK_STATS, M, g3, b3, sc + 2 * 64, sh + 2 * 64, 64);
    bn_apply<64><<<cdiv(M * 64 / 4, 256), 256>>>(xc0, t2, sc + 2 * 64, sh + 2 * 64, M);
    conv_kernel<64, 64, 27><<<cdiv(M, 64), 256>>>(t2, nbr_coarse, w_sub2, xc1, M, M);

    // stage 4: BN4(xc1) -> t3 ; deconv -> xf
    bn_stats1<64><<<NBLK_STATS, 256>>>(xc1, M, part);
    bn_stats2<<<1, 64>>>(part, NBLK_STATS, M, g4, b4, sc + 3 * 64, sh + 3 * 64, 64);
    bn_apply<64><<<cdiv(M * 64 / 4, 256), 256>>>(xc1, t3, sc + 3 * 64, sh + 3 * 64, M);
    deconv_kernel<<<cdiv(N, 64), 256>>>(t3, up_cidx, up_k, w_up, xf, N, 0);
    deconv_kernel<<<cdiv(N, 64), 256>>>(t3, up_cidx, up_k, w_up, xf, N, 4);

    // stage 5: BN5(concat(x1, xf)) -> t4 ; sub3 -> out
    bn_stats1<32><<<NBLK_STATS, 256>>>(x1, N, part);
    bn_stats2<<<1, 64>>>(part, NBLK_STATS, N, g5, b5, sc + 4 * 64, sh + 4 * 64, 32);
    bn_stats1<32><<<NBLK_STATS, 256>>>(xf, N, part);
    bn_stats2<<<1, 64>>>(part, NBLK_STATS, N, g5 + 32, b5 + 32,
                         sc + 4 * 64 + 32, sh + 4 * 64 + 32, 32);
    bn_apply_cat<<<cdiv(N * 16, 256), 256>>>(x1, xf, t4, sc + 4 * 64, sh + 4 * 64, N);
    conv_kernel<64, 32, 27><<<cdiv(N, 64), 256>>>(t4, nbr_fine, w_sub3, outp, N, N);
}

// round 2
// speedup vs baseline: 2.0686x; 2.0686x over previous
#include <cuda_runtime.h>
#include <cstdint>
#include <cstdio>

// ---------------------------------------------------------------------------
// Problem constants
// ---------------------------------------------------------------------------
#define NMAX 200192        // >= N (=200000) and >= M
#define NBLK_STATS 240
#define BN_EPS 1e-4

// ---------------------------------------------------------------------------
// Static device scratch (allocation-free rule: __device__ globals)
// ---------------------------------------------------------------------------
__device__ float  g_t0[(NMAX + 1) * 32];   // bn1(feat), padded
__device__ float  g_x1[NMAX * 32];         // sub1 out (skip)
__device__ float  g_t1[(NMAX + 1) * 32];   // bn2(x1), padded
__device__ float  g_xc0[NMAX * 64];        // down out
__device__ float  g_t2[(NMAX + 1) * 64];   // bn3(xc0), padded
__device__ float  g_xc1[NMAX * 64];        // sub2 out
__device__ float  g_t3[(NMAX + 1) * 64];   // bn4(xc1), padded
__device__ float  g_xf[NMAX * 32];         // deconv out
__device__ float  g_t4[(NMAX + 1) * 64];   // bn5(concat), padded
__device__ double g_part[NBLK_STATS * 128];
__device__ float  g_scale[5 * 64];
__device__ float  g_shift[5 * 64];

// ---------------------------------------------------------------------------
// Packed fp32x2 FMA (sm_103a; only reachable via PTX)
// ---------------------------------------------------------------------------
__device__ __forceinline__ unsigned long long fma2(unsigned long long a,
                                                   unsigned long long b,
                                                   unsigned long long c) {
    unsigned long long d;
    asm("fma.rn.f32x2 %0, %1, %2, %3;" : "=l"(d) : "l"(a), "l"(b), "l"(c));
    return d;
}
__device__ __forceinline__ unsigned long long pack2(float x) {
    unsigned long long r;
    asm("mov.b64 %0, {%1, %1};" : "=l"(r) : "f"(x));
    return r;
}

// ---------------------------------------------------------------------------
// BN stats pass 1: deterministic per-block partial sums (double)
// ---------------------------------------------------------------------------
template <int C>
__global__ __launch_bounds__(256) void bn_stats1(const float* __restrict__ x,
                                                 int rows,
                                                 double* __restrict__ partial) {
    __shared__ double ss[256], sq[256];
    int tid = threadIdx.x;
    long long total = (long long)rows * C;
    double s = 0.0, q = 0.0;
    for (long long i = (long long)blockIdx.x * 256 + tid; i < total;
         i += (long long)gridDim.x * 256) {
        double v = (double)x[i];
        s += v;
        q += v * v;
    }
    ss[tid] = s;
    sq[tid] = q;
    for (int st = 128; st >= C; st >>= 1) {
        __syncthreads();
        if (tid < st) { ss[tid] += ss[tid + st]; sq[tid] += sq[tid + st]; }
    }
    if (tid < C) {
        partial[blockIdx.x * 128 + tid]      = ss[tid];
        partial[blockIdx.x * 128 + 64 + tid] = sq[tid];
    }
}

// BN stats pass 2: reduce partials, emit scale/shift
__global__ void bn_stats2(const double* __restrict__ partial, int nblk, int rows,
                          const float* __restrict__ g, const float* __restrict__ b,
                          float* __restrict__ sc, float* __restrict__ sh, int C) {
    int c = threadIdx.x;
    if (c >= C) return;
    double s = 0.0, q = 0.0;
    for (int i = 0; i < nblk; i++) {
        s += partial[i * 128 + c];
        q += partial[i * 128 + 64 + c];
    }
    double mean = s / rows;
    double var  = q / rows - mean * mean;
    double inv  = 1.0 / sqrt(var + BN_EPS);
    double scale = (double)g[c] * inv;
    sc[c] = (float)scale;
    sh[c] = (float)((double)b[c] - mean * scale);
}

// ---------------------------------------------------------------------------
// BN apply + ReLU, writes padded buffer (pad row zeroed)
// ---------------------------------------------------------------------------
template <int C>
__global__ __launch_bounds__(256) void bn_apply(const float* __restrict__ x,
                                                float* __restrict__ y,
                                                const float* __restrict__ sc,
                                                const float* __restrict__ sh,
                                                int rows) {
    int i = blockIdx.x * blockDim.x + threadIdx.x;
    if (i < C / 4) {
        *reinterpret_cast<float4*>(&y[(size_t)rows * C + 4 * i]) =
            make_float4(0.f, 0.f, 0.f, 0.f);
    }
    int n4 = rows * C / 4;
    if (i < n4) {
        float4 d = reinterpret_cast<const float4*>(x)[i];
        int c0 = (i * 4) % C;
        d.x = fmaxf(fmaf(d.x, __ldg(&sc[c0 + 0]), __ldg(&sh[c0 + 0])), 0.f);
        d.y = fmaxf(fmaf(d.y, __ldg(&sc[c0 + 1]), __ldg(&sh[c0 + 1])), 0.f);
        d.z = fmaxf(fmaf(d.z, __ldg(&sc[c0 + 2]), __ldg(&sh[c0 + 2])), 0.f);
        d.w = fmaxf(fmaf(d.w, __ldg(&sc[c0 + 3]), __ldg(&sh[c0 + 3])), 0.f);
        reinterpret_cast<float4*>(y)[i] = d;
    }
}

// BN apply for concat(skip=x1[:,:32], xf[:,:32]) -> y [rows+1][64]
__global__ __launch_bounds__(256) void bn_apply_cat(const float* __restrict__ x1,
                                                    const float* __restrict__ xf,
                                                    float* __restrict__ y,
                                                    const float* __restrict__ sc,
                                                    const float* __restrict__ sh,
                                                    int rows) {
    int i = blockIdx.x * blockDim.x + threadIdx.x;
    if (i < 16) {
        *reinterpret_cast<float4*>(&y[(size_t)rows * 64 + 4 * i]) =
            make_float4(0.f, 0.f, 0.f, 0.f);
    }
    int n4 = rows * 16;  // float4 groups
    if (i < n4) {
        int row = i / 16, q = i % 16;
        float4 d = (q < 8) ? reinterpret_cast<const float4*>(x1)[row * 8 + q]
                           : reinterpret_cast<const float4*>(xf)[row * 8 + (q - 8)];
        int c0 = q * 4;
        d.x = fmaxf(fmaf(d.x, __ldg(&sc[c0 + 0]), __ldg(&sh[c0 + 0])), 0.f);
        d.y = fmaxf(fmaf(d.y, __ldg(&sc[c0 + 1]), __ldg(&sh[c0 + 1])), 0.f);
        d.z = fmaxf(fmaf(d.z, __ldg(&sc[c0 + 2]), __ldg(&sh[c0 + 2])), 0.f);
        d.w = fmaxf(fmaf(d.w, __ldg(&sc[c0 + 3]), __ldg(&sh[c0 + 3])), 0.f);
        reinterpret_cast<float4*>(y)[i] = d;
    }
}

// ---------------------------------------------------------------------------
// Gather-GEMM sparse conv, register-tiled:
//   out[m, co] = sum_k sum_ci fpad[nbr[k*rows+m], ci] * W[k, ci, co]
// Block: 256 rows, 256 threads. Thread tile: R rows x 8 couts, R = COUT/8.
// Rows interleaved with stride 256/R (bank-conflict-free with XP=CIN+4 pad).
// Per ci-step per thread: 2 W-LDS.128 + R/4 X-LDS.128 vs 4R fma2.
// ---------------------------------------------------------------------------
template <int CIN, int COUT, int K>
__global__ __launch_bounds__(256, 2) void conv_kernel(const float* __restrict__ fpad,
                                                      const int* __restrict__ nbr,
                                                      const float* __restrict__ W,
                                                      float* __restrict__ out,
                                                      int rows, int P) {
    constexpr int NCG = COUT / 8;     // cout groups
    constexpr int R = NCG;            // rows per thread (4 or 8)
    constexpr int RSTRIDE = 256 / R;  // 64 or 32
    constexpr int XP = CIN + 4;       // padded X row pitch (floats)

    extern __shared__ float smem[];
    float* Xs = smem;                          // [256][XP]
    float* Ws = smem + 256 * XP;               // [CIN][COUT]
    int*   idx_s = (int*)(Ws + CIN * COUT);    // [256]

    int tid = threadIdx.x;
    int row0 = blockIdx.x * 256;
    int cg = tid % NCG;
    int rg = tid / NCG;

    unsigned long long acc[R][4];
#pragma unroll
    for (int i = 0; i < R; i++)
#pragma unroll
        for (int j = 0; j < 4; j++) acc[i][j] = 0ull;

    for (int k = 0; k < K; k++) {
        int gr = row0 + tid;
        int myidx = (gr < rows) ? nbr[(size_t)k * rows + gr] : P;
        __syncthreads();  // prev compute done; idx_s/Xs/Ws safe to overwrite
        idx_s[tid] = myidx;
        __syncthreads();

        // gather X tile (coalesced: warp covers full rows)
#pragma unroll
        for (int t = 0; t < CIN / 4; t++) {
            int v = tid + t * 256;
            int rr = v / (CIN / 4), s = v % (CIN / 4);
            float4 val = reinterpret_cast<const float4*>(
                fpad + (size_t)idx_s[rr] * CIN)[s];
            *reinterpret_cast<float4*>(Xs + rr * XP + s * 4) = val;
        }
        // stage tap weights
        const float4* Wk = reinterpret_cast<const float4*>(W + (size_t)k * CIN * COUT);
#pragma unroll
        for (int t = 0; t < CIN * COUT / 1024; t++) {
            int v = tid + t * 256;
            reinterpret_cast<float4*>(Ws)[v] = Wk[v];
        }
        __syncthreads();

#pragma unroll 1
        for (int c4 = 0; c4 < CIN / 4; c4++) {
            float4 xv[R];
#pragma unroll
            for (int i = 0; i < R; i++)
                xv[i] = *reinterpret_cast<const float4*>(
                    Xs + (rg + i * RSTRIDE) * XP + c4 * 4);
#pragma unroll
            for (int ci = 0; ci < 4; ci++) {
                const ulonglong2* wp = reinterpret_cast<const ulonglong2*>(
                    Ws + (c4 * 4 + ci) * COUT + cg * 8);
                ulonglong2 wA = wp[0];
                ulonglong2 wB = wp[1];
#pragma unroll
                for (int i = 0; i < R; i++) {
                    float xs = (ci == 0) ? xv[i].x : (ci == 1) ? xv[i].y
                             : (ci == 2) ? xv[i].z : xv[i].w;
                    unsigned long long xx = pack2(xs);
                    acc[i][0] = fma2(xx, wA.x, acc[i][0]);
                    acc[i][1] = fma2(xx, wA.y, acc[i][1]);
                    acc[i][2] = fma2(xx, wB.x, acc[i][2]);
                    acc[i][3] = fma2(xx, wB.y, acc[i][3]);
                }
            }
        }
    }

#pragma unroll
    for (int i = 0; i < R; i++) {
        int orow = row0 + rg + i * RSTRIDE;
        if (orow < rows) {
            float* op = out + (size_t)orow * COUT + cg * 8;
            float2 a0 = *reinterpret_cast<float2*>(&acc[i][0]);
            float2 a1 = *reinterpret_cast<float2*>(&acc[i][1]);
            float2 a2 = *reinterpret_cast<float2*>(&acc[i][2]);
            float2 a3 = *reinterpret_cast<float2*>(&acc[i][3]);
            reinterpret_cast<float4*>(op)[0] = make_float4(a0.x, a0.y, a1.x, a1.y);
            reinterpret_cast<float4*>(op)[1] = make_float4(a2.x, a2.y, a3.x, a3.y);
        }
    }
}

// ---------------------------------------------------------------------------
// Stride-2 transpose conv (deconv): out[n] = g[up_cidx[n]] @ W[up_k[n]]
// Two predicated passes over k (4 taps of W fit 32KB smem each).
// ---------------------------------------------------------------------------
__global__ __launch_bounds__(256) void deconv_kernel(const float* __restrict__ g,
                                                     const int* __restrict__ up_cidx,
                                                     const int* __restrict__ up_k,
                                                     const float* __restrict__ Wup,
                                                     float* __restrict__ out,
                                                     int nrows, int kbase) {
    __shared__ float Ws[4][64][32];  // 32 KB
    int tid = threadIdx.x;
    const float4* src = reinterpret_cast<const float4*>(Wup + (size_t)kbase * 64 * 32);
    for (int v = tid; v < 4 * 64 * 32 / 4; v += 256)
        reinterpret_cast<float4*>(&Ws[0][0][0])[v] = src[v];
    __syncthreads();

    int warp = tid >> 5, lane = tid & 31;
    int base = blockIdx.x * 64 + warp * 8;
#pragma unroll
    for (int i = 0; i < 8; i++) {
        int row = base + i;
        if (row >= nrows) break;
        int k = up_k[row] - kbase;
        if ((unsigned)k < 4u) {
            int cid = up_cidx[row];
            const float* grow = g + (size_t)cid * 64;
            float xa = grow[lane], xb = grow[lane + 32];
            float acc = 0.f;
#pragma unroll
            for (int cin = 0; cin < 64; cin++) {
                float xv = __shfl_sync(0xFFFFFFFFu, (cin < 32) ? xa : xb, cin & 31);
                acc = fmaf(xv, Ws[k][cin][lane], acc);
            }
            out[(size_t)row * 32 + lane] = acc;
        }
    }
}

// ---------------------------------------------------------------------------
// Host launcher
// ---------------------------------------------------------------------------
static void* sym_addr(const void* s) {
    void* p = nullptr;
    cudaGetSymbolAddress(&p, s);
    return p;
}

template <int CIN, int COUT>
static constexpr int conv_smem() {
    return 256 * (CIN + 4) * 4 + CIN * COUT * 4 + 256 * 4;
}

extern "C" void kernel_launch(void* const* d_in, const int* in_sizes, int n_in,
                              void* d_out, int out_size) {
    const float* feat    = (const float*)d_in[0];
    const float* w_sub1  = (const float*)d_in[1];
    const float* w_down  = (const float*)d_in[2];
    const float* w_sub2  = (const float*)d_in[3];
    const float* w_up    = (const float*)d_in[4];
    const float* w_sub3  = (const float*)d_in[5];
    const float* g1 = (const float*)d_in[6];  const float* b1 = (const float*)d_in[7];
    const float* g2 = (const float*)d_in[8];  const float* b2 = (const float*)d_in[9];
    const float* g3 = (const float*)d_in[10]; const float* b3 = (const float*)d_in[11];
    const float* g4 = (const float*)d_in[12]; const float* b4 = (const float*)d_in[13];
    const float* g5 = (const float*)d_in[14]; const float* b5 = (const float*)d_in[15];
    const int* nbr_fine   = (const int*)d_in[16];
    const int* nbr_coarse = (const int*)d_in[17];
    const int* down_idx   = (const int*)d_in[18];
    const int* up_cidx    = (const int*)d_in[19];
    const int* up_k       = (const int*)d_in[20];

    int N = in_sizes[0] / 32;
    int M = in_sizes[18] / 8;

    float*  t0   = (float*)sym_addr(g_t0);
    float*  x1   = (float*)sym_addr(g_x1);
    float*  t1   = (float*)sym_addr(g_t1);
    float*  xc0  = (float*)sym_addr(g_xc0);
    float*  t2   = (float*)sym_addr(g_t2);
    float*  xc1  = (float*)sym_addr(g_xc1);
    float*  t3   = (float*)sym_addr(g_t3);
    float*  xf   = (float*)sym_addr(g_xf);
    float*  t4   = (float*)sym_addr(g_t4);
    double* part = (double*)sym_addr(g_part);
    float*  sc   = (float*)sym_addr(g_scale);
    float*  sh   = (float*)sym_addr(g_shift);
    float*  outp = (float*)d_out;

    auto cdiv = [](int a, int b) { return (a + b - 1) / b; };

    // raise dynamic smem limits (idempotent; host-side, capture-safe)
    cudaFuncSetAttribute((const void*)conv_kernel<32, 32, 27>,
                         cudaFuncAttributeMaxDynamicSharedMemorySize,
                         conv_smem<32, 32>());
    cudaFuncSetAttribute((const void*)conv_kernel<32, 64, 8>,
                         cudaFuncAttributeMaxDynamicSharedMemorySize,
                         conv_smem<32, 64>());
    cudaFuncSetAttribute((const void*)conv_kernel<64, 64, 27>,
                         cudaFuncAttributeMaxDynamicSharedMemorySize,
                         conv_smem<64, 64>());
    cudaFuncSetAttribute((const void*)conv_kernel<64, 32, 27>,
                         cudaFuncAttributeMaxDynamicSharedMemorySize,
                         conv_smem<64, 32>());

    // stage 1: BN1(feat) -> t0 ; sub1 -> x1
    bn_stats1<32><<<NBLK_STATS, 256>>>(feat, N, part);
    bn_stats2<<<1, 64>>>(part, NBLK_STATS, N, g1, b1, sc + 0 * 64, sh + 0 * 64, 32);
    bn_apply<32><<<cdiv(N * 32 / 4, 256), 256>>>(feat, t0, sc + 0 * 64, sh + 0 * 64, N);
    conv_kernel<32, 32, 27><<<cdiv(N, 256), 256, conv_smem<32, 32>()>>>(
        t0, nbr_fine, w_sub1, x1, N, N);

    // stage 2: BN2(x1) -> t1 ; down -> xc0
    bn_stats1<32><<<NBLK_STATS, 256>>>(x1, N, part);
    bn_stats2<<<1, 64>>>(part, NBLK_STATS, N, g2, b2, sc + 1 * 64, sh + 1 * 64, 32);
    bn_apply<32><<<cdiv(N * 32 / 4, 256), 256>>>(x1, t1, sc + 1 * 64, sh + 1 * 64, N);
    conv_kernel<32, 64, 8><<<cdiv(M, 256), 256, conv_smem<32, 64>()>>>(
        t1, down_idx, w_down, xc0, M, N);

    // stage 3: BN3(xc0) -> t2 ; sub2 -> xc1
    bn_stats1<64><<<NBLK_STATS, 256>>>(xc0, M, part);
    bn_stats2<<<1, 64>>>(part, NBLK_STATS, M, g3, b3, sc + 2 * 64, sh + 2 * 64, 64);
    bn_apply<64><<<cdiv(M * 64 / 4, 256), 256>>>(xc0, t2, sc + 2 * 64, sh + 2 * 64, M);
    conv_kernel<64, 64, 27><<<cdiv(M, 256), 256, conv_smem<64, 64>()>>>(
        t2, nbr_coarse, w_sub2, xc1, M, M);

    // stage 4: BN4(xc1) -> t3 ; deconv -> xf
    bn_stats1<64><<<NBLK_STATS, 256>>>(xc1, M, part);
    bn_stats2<<<1, 64>>>(part, NBLK_STATS, M, g4, b4, sc + 3 * 64, sh + 3 * 64, 64);
    bn_apply<64><<<cdiv(M * 64 / 4, 256), 256>>>(xc1, t3, sc + 3 * 64, sh + 3 * 64, M);
    deconv_kernel<<<cdiv(N, 64), 256>>>(t3, up_cidx, up_k, w_up, xf, N, 0);
    deconv_kernel<<<cdiv(N, 64), 256>>>(t3, up_cidx, up_k, w_up, xf, N, 4);

    // stage 5: BN5(concat(x1, xf)) -> t4 ; sub3 -> out
    bn_stats1<32><<<NBLK_STATS, 256>>>(x1, N, part);
    bn_stats2<<<1, 64>>>(part, NBLK_STATS, N, g5, b5, sc + 4 * 64, sh + 4 * 64, 32);
    bn_stats1<32><<<NBLK_STATS, 256>>>(xf, N, part);
    bn_stats2<<<1, 64>>>(part, NBLK_STATS, N, g5 + 32, b5 + 32,
                         sc + 4 * 64 + 32, sh + 4 * 64 + 32, 32);
    bn_apply_cat<<<cdiv(N * 16, 256), 256>>>(x1, xf, t4, sc + 4 * 64, sh + 4 * 64, N);
    conv_kernel<64, 32, 27><<<cdiv(N, 256), 256, conv_smem<64, 32>()>>>(
        t4, nbr_fine, w_sub3, outp, N, N);
}